// round 14
// baseline (speedup 1.0000x reference)
#include <cuda_runtime.h>
#include <cuda_fp16.h>
#include <math.h>
#include <stdint.h>

#define T_LEN   512
#define B_SZ    128
#define H_SZ    1024
#define NIN     128
#define NOUT    128
#define ALPHA_F 0.25f
#define LEAK_F  0.75f
#define NSCALE  0.025f
#define GRID_RNN 128
#define BH      (B_SZ * H_SZ)

// rnn SMEM (bytes): A tile 64 x 528 (single fp16); B tile 64 x 528 hi+lo
#define PITCH  528
#define A_SM   0
#define B_HI   33792
#define B_LO   67584
#define SM_ALLOC 101376

// pre/post SMEM: A single (128 x 528), B hi+lo (64 x 528 each)
#define P_A    0
#define P_BH   67584
#define P_BL   101376
#define P_SMEM 135168

// ---------------- device scratch ----------------
__device__ float g_c[(size_t)T_LEN * BH];
__device__ __half g_a[BH];                       // tanh(h) as fp16 (single)
__device__ float g_p[4 * BH];                    // 4 split-K partials
__device__ unsigned g_arr[GRID_RNN * 32];        // arrival flags, one 128B line each
__device__ unsigned g_rel[GRID_RNN * 32];        // release flags, one 128B line each

// fp16 mma m16n8k16, fp32 accum (baseline PTX, works on compute_103)
__device__ __forceinline__ void mma_f16(float& c0, float& c1, float& c2, float& c3,
                                        uint32_t a0, uint32_t a1, uint32_t a2, uint32_t a3,
                                        uint32_t b0, uint32_t b1) {
    asm volatile(
        "mma.sync.aligned.m16n8k16.row.col.f32.f16.f16.f32 "
        "{%0,%1,%2,%3}, {%4,%5,%6,%7}, {%8,%9}, {%0,%1,%2,%3};"
        : "+f"(c0), "+f"(c1), "+f"(c2), "+f"(c3)
        : "r"(a0), "r"(a1), "r"(a2), "r"(a3), "r"(b0), "r"(b1));
}

__device__ __forceinline__ uint32_t pack_h2(float a, float b) {
    __half x = __float2half(a), y = __float2half(b);
    return (uint32_t)__half_as_ushort(x) | ((uint32_t)__half_as_ushort(y) << 16);
}

// fast tanh via MUFU exp: abs error ~1e-6, negligible vs 2.9e-4 budget
__device__ __forceinline__ float tfast(float x) {
    float e = __expf(2.0f * x);
    return 1.0f - 2.0f / (e + 1.0f);
}

// ---------------- init ----------------
__global__ void init_kernel(const float* __restrict__ hidden) {
    int i = blockIdx.x * blockDim.x + threadIdx.x;
    if (i < GRID_RNN * 32) { g_arr[i] = 0u; g_rel[i] = 0u; }
    if (i < BH) {
        g_a[i] = __float2half(tanhf(hidden[i]));
    }
}

// ------- pre (tensor cores): c = alpha*(x@Win^T + b_in + b_hh) + 0.025*noise
__global__ void __launch_bounds__(256, 1) pre_tc_kernel(
    const float* __restrict__ x, const float* __restrict__ noise,
    const float* __restrict__ w_in, const float* __restrict__ b_in,
    const float* __restrict__ b_hh)
{
    extern __shared__ char sm[];
    const int tid = threadIdx.x;
    const int c0 = blockIdx.x * 64;
    const int r0 = blockIdx.y * 128;
    const int wid = tid >> 5, lane = tid & 31;
    const int wm = (wid & 3) * 32;
    const int wn = (wid >> 2) * 32;
    const int gq = lane >> 2, q = lane & 3;

    float acc[2][4][4] = {};

    const char* pA  = sm + P_A  + (wm + gq) * PITCH + q * 4;
    const char* pBh = sm + P_BH + (wn + gq) * PITCH + q * 4;
    const char* pBl = sm + P_BL + (wn + gq) * PITCH + q * 4;

    #pragma unroll
    for (int ch = 0; ch < 2; ch++) {
        const int kc = ch * 64;
        __syncthreads();
        #pragma unroll
        for (int i = 0; i < 8; i++) {
            int idx = i * 256 + tid;
            int r = idx >> 4, c4 = idx & 15;
            int rr = r0 + r;
            const float* src = x + ((size_t)(rr & 127) * T_LEN + (rr >> 7)) * NIN + kc + c4 * 4;
            float4 v = __ldcg((const float4*)src);
            *(uint2*)(sm + P_A + r * PITCH + c4 * 8) =
                make_uint2(pack_h2(v.x, v.y), pack_h2(v.z, v.w));
        }
        #pragma unroll
        for (int i = 0; i < 4; i++) {
            int idx = i * 256 + tid;
            int r = idx >> 4, c4 = idx & 15;
            float4 v = __ldcg((const float4*)(w_in + (size_t)(c0 + r) * NIN + kc + c4 * 4));
            float hx = __half2float(__float2half(v.x));
            float hy = __half2float(__float2half(v.y));
            float hz = __half2float(__float2half(v.z));
            float hw = __half2float(__float2half(v.w));
            *(uint2*)(sm + P_BH + r * PITCH + c4 * 8) =
                make_uint2(pack_h2(v.x, v.y), pack_h2(v.z, v.w));
            *(uint2*)(sm + P_BL + r * PITCH + c4 * 8) =
                make_uint2(pack_h2(v.x - hx, v.y - hy), pack_h2(v.z - hz, v.w - hw));
        }
        __syncthreads();

        #pragma unroll
        for (int kk = 0; kk < 4; kk++) {
            const int kb = kk * 32;
            uint32_t ah[2][4], bhf[4][2], blf[4][2];
            #pragma unroll
            for (int mt = 0; mt < 2; mt++) {
                const int mo = mt * 16 * PITCH;
                ah[mt][0] = *(const uint32_t*)(pA + mo + kb);
                ah[mt][1] = *(const uint32_t*)(pA + mo + 8 * PITCH + kb);
                ah[mt][2] = *(const uint32_t*)(pA + mo + kb + 16);
                ah[mt][3] = *(const uint32_t*)(pA + mo + 8 * PITCH + kb + 16);
            }
            #pragma unroll
            for (int j = 0; j < 4; j++) {
                bhf[j][0] = *(const uint32_t*)(pBh + j * 8 * PITCH + kb);
                bhf[j][1] = *(const uint32_t*)(pBh + j * 8 * PITCH + kb + 16);
                blf[j][0] = *(const uint32_t*)(pBl + j * 8 * PITCH + kb);
                blf[j][1] = *(const uint32_t*)(pBl + j * 8 * PITCH + kb + 16);
            }
            #pragma unroll
            for (int mt = 0; mt < 2; mt++)
                #pragma unroll
                for (int j = 0; j < 4; j++) {
                    mma_f16(acc[mt][j][0], acc[mt][j][1], acc[mt][j][2], acc[mt][j][3],
                            ah[mt][0], ah[mt][1], ah[mt][2], ah[mt][3], bhf[j][0], bhf[j][1]);
                    mma_f16(acc[mt][j][0], acc[mt][j][1], acc[mt][j][2], acc[mt][j][3],
                            ah[mt][0], ah[mt][1], ah[mt][2], ah[mt][3], blf[j][0], blf[j][1]);
                }
        }
    }

    #pragma unroll
    for (int j = 0; j < 4; j++) {
        int col = c0 + wn + j * 8 + q * 2;
        float bi0 = b_in[col] + b_hh[col];
        float bi1 = b_in[col + 1] + b_hh[col + 1];
        #pragma unroll
        for (int mt = 0; mt < 2; mt++) {
            int row = r0 + wm + mt * 16 + gq;
            float2 n0 = __ldcg((const float2*)(noise + (size_t)row * H_SZ + col));
            float2 n1 = __ldcg((const float2*)(noise + (size_t)(row + 8) * H_SZ + col));
            float2 v0, v1;
            v0.x = ALPHA_F * (acc[mt][j][0] + bi0) + NSCALE * n0.x;
            v0.y = ALPHA_F * (acc[mt][j][1] + bi1) + NSCALE * n0.y;
            v1.x = ALPHA_F * (acc[mt][j][2] + bi0) + NSCALE * n1.x;
            v1.y = ALPHA_F * (acc[mt][j][3] + bi1) + NSCALE * n1.y;
            *(float2*)(g_c + (size_t)row * H_SZ + col) = v0;
            *(float2*)(g_c + (size_t)(row + 8) * H_SZ + col) = v1;
        }
    }
}

// ---- atomic-free hierarchical grid barrier ---------------------------------
// Arrival: each CTA stores epoch to its own 128B line (no RMW).
// CTA 0: 128 threads poll 128 distinct arrival lines (1 reader/line), then
// release by storing to 128 distinct release lines. Waiters poll own line.
__device__ __forceinline__ void grid_bar(int cta, unsigned epoch) {
    __syncthreads();
    if (threadIdx.x == 0) {
        __threadfence();
        *(volatile unsigned*)&g_arr[cta * 32] = epoch;
    }
    if (cta == 0) {
        if (threadIdx.x < GRID_RNN) {
            while (*(volatile unsigned*)&g_arr[threadIdx.x * 32] < epoch) { }
        }
        __syncthreads();
        if (threadIdx.x < GRID_RNN) {
            __threadfence();
            *(volatile unsigned*)&g_rel[threadIdx.x * 32] = epoch;
        }
    } else {
        if (threadIdx.x == 0) {
            while (*(volatile unsigned*)&g_rel[cta * 32] < epoch) { }
            __threadfence();
        }
    }
    __syncthreads();
}

// ---------------- persistent recurrent kernel (R13 structure) ---------------
// 128 CTAs = 4 k-splits x 2 b-tiles x 16 h-tiles. 256 threads, 8 warps 16x32.
__global__ void __launch_bounds__(256, 1) rnn_kernel(
    float* __restrict__ hid_list, float* __restrict__ h_final,
    const float* __restrict__ w_hh, const float* __restrict__ hidden0)
{
    extern __shared__ char sm[];
    const int cta = blockIdx.x;
    const int ks = cta & 3;
    const int bt = (cta >> 2) & 1;
    const int ht = cta >> 3;
    const int tid = threadIdx.x;
    const int r0 = bt * 64, c0 = ht * 64, k0 = ks * 256;

    // resident weight slice -> fp16 hi/lo (once)
    for (int e = tid; e < 64 * 256; e += 256) {
        int n = e >> 8, k = e & 255;
        float w = w_hh[(size_t)(c0 + n) * H_SZ + k0 + k];
        __half wh = __float2half(w);
        __half wl = __float2half(w - __half2float(wh));
        *(__half*)(sm + B_HI + n * PITCH + k * 2) = wh;
        *(__half*)(sm + B_LO + n * PITCH + k * 2) = wl;
    }
    __syncthreads();

    const int wid = tid >> 5, lane = tid & 31;
    const int wm = (wid & 3) * 16;
    const int wn = (wid >> 2) * 32;
    const int gq = lane >> 2;
    const int q  = lane & 3;

    float* pout = g_p + (size_t)ks * BH;
    const char* pA  = sm + A_SM + (wm + gq) * PITCH + q * 4;
    const char* pBh = sm + B_HI + (wn + gq) * PITCH + q * 4;
    const char* pBl = sm + B_LO + (wn + gq) * PITCH + q * 4;

    const int e  = cta * 1024 + tid * 4;
    const int eb = e >> 10, eh = e & 1023;

    float4 hreg = *(const float4*)(hidden0 + e);
    unsigned epoch = 0;

    for (int t = 0; t < T_LEN; t++) {
        float4 cv = __ldcg((const float4*)(g_c + (size_t)t * BH + e));

        // stage A slice: 64 rows x 256 fp16 = 32KB
        #pragma unroll
        for (int i = 0; i < 4; i++) {
            int idx = i * 256 + tid;
            int r = idx >> 4, cc = idx & 15;
            size_t goff = (size_t)(r0 + r) * 2048 + (size_t)k0 * 2 + cc * 32;
            uint4 v0 = __ldcg((const uint4*)((const char*)g_a + goff));
            uint4 v1 = __ldcg((const uint4*)((const char*)g_a + goff + 16));
            *(uint4*)(sm + A_SM + r * PITCH + cc * 32) = v0;
            *(uint4*)(sm + A_SM + r * PITCH + cc * 32 + 16) = v1;
        }
        __syncthreads();

        // fp16 2-product GEMM: acc = A*Bhi + A*Blo
        float acc[4][4] = {};
        #pragma unroll
        for (int kk = 0; kk < 16; kk++) {
            const int kb = kk * 32;
            uint32_t a0 = *(const uint32_t*)(pA + kb);
            uint32_t a1 = *(const uint32_t*)(pA + 8 * PITCH + kb);
            uint32_t a2 = *(const uint32_t*)(pA + kb + 16);
            uint32_t a3 = *(const uint32_t*)(pA + 8 * PITCH + kb + 16);
            #pragma unroll
            for (int j = 0; j < 4; j++) {
                uint32_t bh0 = *(const uint32_t*)(pBh + j * 8 * PITCH + kb);
                uint32_t bh1 = *(const uint32_t*)(pBh + j * 8 * PITCH + kb + 16);
                uint32_t bl0 = *(const uint32_t*)(pBl + j * 8 * PITCH + kb);
                uint32_t bl1 = *(const uint32_t*)(pBl + j * 8 * PITCH + kb + 16);
                mma_f16(acc[j][0], acc[j][1], acc[j][2], acc[j][3],
                        a0, a1, a2, a3, bh0, bh1);
                mma_f16(acc[j][0], acc[j][1], acc[j][2], acc[j][3],
                        a0, a1, a2, a3, bl0, bl1);
            }
        }
        #pragma unroll
        for (int j = 0; j < 4; j++) {
            float* pp = pout + (size_t)(r0 + wm + gq) * H_SZ + c0 + wn + j * 8 + q * 2;
            *(float2*)pp = make_float2(acc[j][0], acc[j][1]);
            *(float2*)(pp + 8 * H_SZ) = make_float2(acc[j][2], acc[j][3]);
        }

        grid_bar(cta, ++epoch);

        {
            float4 p0 = *(const float4*)(g_p + e);
            float4 p1 = *(const float4*)(g_p + 1 * BH + e);
            float4 p2 = *(const float4*)(g_p + 2 * BH + e);
            float4 p3 = *(const float4*)(g_p + 3 * BH + e);
            float4 hn;
            hn.x = LEAK_F * hreg.x + ALPHA_F * (p0.x + p1.x + p2.x + p3.x) + cv.x;
            hn.y = LEAK_F * hreg.y + ALPHA_F * (p0.y + p1.y + p2.y + p3.y) + cv.y;
            hn.z = LEAK_F * hreg.z + ALPHA_F * (p0.z + p1.z + p2.z + p3.z) + cv.z;
            hn.w = LEAK_F * hreg.w + ALPHA_F * (p0.w + p1.w + p2.w + p3.w) + cv.w;
            hreg = hn;
            *(float4*)(hid_list + ((size_t)eb * T_LEN + t) * H_SZ + eh) = hn;
            if (t == T_LEN - 1) *(float4*)(h_final + e) = hn;

            float t0 = tfast(hn.x), t1 = tfast(hn.y), t2 = tfast(hn.z), t3 = tfast(hn.w);
            uint2 hw;
            hw.x = pack_h2(t0, t1);
            hw.y = pack_h2(t2, t3);
            *(uint2*)((char*)g_a + (size_t)e * 2) = hw;
        }

        grid_bar(cta, ++epoch);
    }
}

// ------- post (tensor cores, fp16 2-product) ---------------------------------
__global__ void __launch_bounds__(256, 1) post_tc_kernel(
    const float* __restrict__ hid_list, const float* __restrict__ w_out,
    const float* __restrict__ b_out, float* __restrict__ out_list)
{
    extern __shared__ char sm[];
    const int tid = threadIdx.x;
    const int c0 = blockIdx.x * 64;
    const int r0 = blockIdx.y * 128;
    const int wid = tid >> 5, lane = tid & 31;
    const int wm = (wid & 3) * 32;
    const int wn = (wid >> 2) * 32;
    const int gq = lane >> 2, q = lane & 3;

    float acc[2][4][4] = {};

    const char* pA  = sm + P_A  + (wm + gq) * PITCH + q * 4;
    const char* pBh = sm + P_BH + (wn + gq) * PITCH + q * 4;
    const char* pBl = sm + P_BL + (wn + gq) * PITCH + q * 4;

    for (int ch = 0; ch < 16; ch++) {
        const int kc = ch * 64;
        __syncthreads();
        #pragma unroll
        for (int i = 0; i < 8; i++) {
            int idx = i * 256 + tid;
            int r = idx >> 4, c4 = idx & 15;
            float4 v = __ldcg((const float4*)(hid_list + (size_t)(r0 + r) * H_SZ + kc + c4 * 4));
            *(uint2*)(sm + P_A + r * PITCH + c4 * 8) =
                make_uint2(pack_h2(v.x, v.y), pack_h2(v.z, v.w));
        }
        #pragma unroll
        for (int i = 0; i < 4; i++) {
            int idx = i * 256 + tid;
            int r = idx >> 4, c4 = idx & 15;
            float4 v = __ldcg((const float4*)(w_out + (size_t)(c0 + r) * H_SZ + kc + c4 * 4));
            float hx = __half2float(__float2half(v.x));
            float hy = __half2float(__float2half(v.y));
            float hz = __half2float(__float2half(v.z));
            float hw = __half2float(__float2half(v.w));
            *(uint2*)(sm + P_BH + r * PITCH + c4 * 8) =
                make_uint2(pack_h2(v.x, v.y), pack_h2(v.z, v.w));
            *(uint2*)(sm + P_BL + r * PITCH + c4 * 8) =
                make_uint2(pack_h2(v.x - hx, v.y - hy), pack_h2(v.z - hz, v.w - hw));
        }
        __syncthreads();

        #pragma unroll
        for (int kk = 0; kk < 4; kk++) {
            const int kb = kk * 32;
            uint32_t ah[2][4], bhf[4][2], blf[4][2];
            #pragma unroll
            for (int mt = 0; mt < 2; mt++) {
                const int mo = mt * 16 * PITCH;
                ah[mt][0] = *(const uint32_t*)(pA + mo + kb);
                ah[mt][1] = *(const uint32_t*)(pA + mo + 8 * PITCH + kb);
                ah[mt][2] = *(const uint32_t*)(pA + mo + kb + 16);
                ah[mt][3] = *(const uint32_t*)(pA + mo + 8 * PITCH + kb + 16);
            }
            #pragma unroll
            for (int j = 0; j < 4; j++) {
                bhf[j][0] = *(const uint32_t*)(pBh + j * 8 * PITCH + kb);
                bhf[j][1] = *(const uint32_t*)(pBh + j * 8 * PITCH + kb + 16);
                blf[j][0] = *(const uint32_t*)(pBl + j * 8 * PITCH + kb);
                blf[j][1] = *(const uint32_t*)(pBl + j * 8 * PITCH + kb + 16);
            }
            #pragma unroll
            for (int mt = 0; mt < 2; mt++)
                #pragma unroll
                for (int j = 0; j < 4; j++) {
                    mma_f16(acc[mt][j][0], acc[mt][j][1], acc[mt][j][2], acc[mt][j][3],
                            ah[mt][0], ah[mt][1], ah[mt][2], ah[mt][3], bhf[j][0], bhf[j][1]);
                    mma_f16(acc[mt][j][0], acc[mt][j][1], acc[mt][j][2], acc[mt][j][3],
                            ah[mt][0], ah[mt][1], ah[mt][2], ah[mt][3], blf[j][0], blf[j][1]);
                }
        }
    }

    #pragma unroll
    for (int mt = 0; mt < 2; mt++) {
        #pragma unroll
        for (int j = 0; j < 4; j++) {
            int col = c0 + wn + j * 8 + q * 2;
            float b0 = b_out[col], b1 = b_out[col + 1];
            int row = r0 + wm + mt * 16 + gq;
            float2 v0, v1;
            v0.x = fminf(fmaxf(acc[mt][j][0] + b0, -20.0f), 20.0f);
            v0.y = fminf(fmaxf(acc[mt][j][1] + b1, -20.0f), 20.0f);
            v1.x = fminf(fmaxf(acc[mt][j][2] + b0, -20.0f), 20.0f);
            v1.y = fminf(fmaxf(acc[mt][j][3] + b1, -20.0f), 20.0f);
            *(float2*)(out_list + (size_t)row * NOUT + col) = v0;
            *(float2*)(out_list + (size_t)(row + 8) * NOUT + col) = v1;
        }
    }
}

extern "C" void kernel_launch(void* const* d_in, const int* in_sizes, int n_in,
                              void* d_out, int out_size) {
    const float* x       = (const float*)d_in[0];
    const float* hidden0 = (const float*)d_in[1];
    const float* noise   = (const float*)d_in[2];
    const float* w_in_w  = (const float*)d_in[3];
    const float* w_in_b  = (const float*)d_in[4];
    const float* w_hh_w  = (const float*)d_in[5];
    const float* w_hh_b  = (const float*)d_in[6];
    const float* w_out_w = (const float*)d_in[7];
    const float* w_out_b = (const float*)d_in[8];

    float* out      = (float*)d_out;
    float* hid_list = out;
    float* out_list = out + (size_t)B_SZ * T_LEN * H_SZ;
    float* h_final  = out_list + (size_t)B_SZ * T_LEN * NOUT;

    cudaFuncSetAttribute(rnn_kernel, cudaFuncAttributeMaxDynamicSharedMemorySize, SM_ALLOC);
    cudaFuncSetAttribute(pre_tc_kernel, cudaFuncAttributeMaxDynamicSharedMemorySize, P_SMEM);
    cudaFuncSetAttribute(post_tc_kernel, cudaFuncAttributeMaxDynamicSharedMemorySize, P_SMEM);
    init_kernel<<<(BH + 255) / 256, 256>>>(hidden0);
    pre_tc_kernel<<<dim3(H_SZ / 64, (T_LEN * B_SZ) / 128), 256, P_SMEM>>>(
        x, noise, w_in_w, w_in_b, w_hh_b);
    rnn_kernel<<<GRID_RNN, 256, SM_ALLOC>>>(hid_list, h_final, w_hh_w, hidden0);
    post_tc_kernel<<<dim3(NOUT / 64, (B_SZ * T_LEN) / 128), 256, P_SMEM>>>(
        hid_list, w_out_w, w_out_b, out_list);
}

// round 15
// speedup vs baseline: 1.5352x; 1.5352x over previous
#include <cuda_runtime.h>
#include <cuda_fp16.h>
#include <math.h>
#include <stdint.h>

#define T_LEN   512
#define B_SZ    128
#define H_SZ    1024
#define NIN     128
#define NOUT    128
#define ALPHA_F 0.25f
#define LEAK_F  0.75f
#define NSCALE  0.025f
#define GRID_RNN 128
#define BH      (B_SZ * H_SZ)

// rnn SMEM: A 32 rows x 2064B (fp16, full K=1024); B 32 x 2064 hi+lo
#define APITCH 2064
#define A_SM   0
#define B_HI   66048
#define B_LO   132096
#define SM_ALLOC 198144

// pre/post SMEM (R13 proven): A single (128 x 528), B hi+lo (64 x 528 each)
#define PITCH  528
#define P_A    0
#define P_BH   67584
#define P_BL   101376
#define P_SMEM 135168

// ---------------- device scratch ----------------
__device__ float g_c[(size_t)T_LEN * BH];
__device__ __half g_a[BH];                       // tanh(h) fp16
__device__ unsigned g_bar_count;
__device__ unsigned g_rel[GRID_RNN * 32];

__device__ __forceinline__ void mma_f16(float& c0, float& c1, float& c2, float& c3,
                                        uint32_t a0, uint32_t a1, uint32_t a2, uint32_t a3,
                                        uint32_t b0, uint32_t b1) {
    asm volatile(
        "mma.sync.aligned.m16n8k16.row.col.f32.f16.f16.f32 "
        "{%0,%1,%2,%3}, {%4,%5,%6,%7}, {%8,%9}, {%0,%1,%2,%3};"
        : "+f"(c0), "+f"(c1), "+f"(c2), "+f"(c3)
        : "r"(a0), "r"(a1), "r"(a2), "r"(a3), "r"(b0), "r"(b1));
}

__device__ __forceinline__ uint32_t pack_h2(float a, float b) {
    __half x = __float2half(a), y = __float2half(b);
    return (uint32_t)__half_as_ushort(x) | ((uint32_t)__half_as_ushort(y) << 16);
}

// ---------------- init ----------------
__global__ void init_kernel(const float* __restrict__ hidden) {
    int i = blockIdx.x * blockDim.x + threadIdx.x;
    if (i == 0) g_bar_count = 0u;
    if (i < GRID_RNN * 32) g_rel[i] = 0u;
    if (i < BH) g_a[i] = __float2half(tanhf(hidden[i]));
}

// ------- pre (tensor cores, R13 proven) --------------------------------------
__global__ void __launch_bounds__(256, 1) pre_tc_kernel(
    const float* __restrict__ x, const float* __restrict__ noise,
    const float* __restrict__ w_in, const float* __restrict__ b_in,
    const float* __restrict__ b_hh)
{
    extern __shared__ char sm[];
    const int tid = threadIdx.x;
    const int c0 = blockIdx.x * 64;
    const int r0 = blockIdx.y * 128;
    const int wid = tid >> 5, lane = tid & 31;
    const int wm = (wid & 3) * 32;
    const int wn = (wid >> 2) * 32;
    const int gq = lane >> 2, q = lane & 3;

    float acc[2][4][4] = {};
    const char* pA  = sm + P_A  + (wm + gq) * PITCH + q * 4;
    const char* pBh = sm + P_BH + (wn + gq) * PITCH + q * 4;
    const char* pBl = sm + P_BL + (wn + gq) * PITCH + q * 4;

    #pragma unroll
    for (int ch = 0; ch < 2; ch++) {
        const int kc = ch * 64;
        __syncthreads();
        #pragma unroll
        for (int i = 0; i < 8; i++) {
            int idx = i * 256 + tid;
            int r = idx >> 4, c4 = idx & 15;
            int rr = r0 + r;
            const float* src = x + ((size_t)(rr & 127) * T_LEN + (rr >> 7)) * NIN + kc + c4 * 4;
            float4 v = __ldcg((const float4*)src);
            *(uint2*)(sm + P_A + r * PITCH + c4 * 8) =
                make_uint2(pack_h2(v.x, v.y), pack_h2(v.z, v.w));
        }
        #pragma unroll
        for (int i = 0; i < 4; i++) {
            int idx = i * 256 + tid;
            int r = idx >> 4, c4 = idx & 15;
            float4 v = __ldcg((const float4*)(w_in + (size_t)(c0 + r) * NIN + kc + c4 * 4));
            float hx = __half2float(__float2half(v.x));
            float hy = __half2float(__float2half(v.y));
            float hz = __half2float(__float2half(v.z));
            float hw = __half2float(__float2half(v.w));
            *(uint2*)(sm + P_BH + r * PITCH + c4 * 8) =
                make_uint2(pack_h2(v.x, v.y), pack_h2(v.z, v.w));
            *(uint2*)(sm + P_BL + r * PITCH + c4 * 8) =
                make_uint2(pack_h2(v.x - hx, v.y - hy), pack_h2(v.z - hz, v.w - hw));
        }
        __syncthreads();

        #pragma unroll
        for (int kk = 0; kk < 4; kk++) {
            const int kb = kk * 32;
            uint32_t ah[2][4], bhf[4][2], blf[4][2];
            #pragma unroll
            for (int mt = 0; mt < 2; mt++) {
                const int mo = mt * 16 * PITCH;
                ah[mt][0] = *(const uint32_t*)(pA + mo + kb);
                ah[mt][1] = *(const uint32_t*)(pA + mo + 8 * PITCH + kb);
                ah[mt][2] = *(const uint32_t*)(pA + mo + kb + 16);
                ah[mt][3] = *(const uint32_t*)(pA + mo + 8 * PITCH + kb + 16);
            }
            #pragma unroll
            for (int j = 0; j < 4; j++) {
                bhf[j][0] = *(const uint32_t*)(pBh + j * 8 * PITCH + kb);
                bhf[j][1] = *(const uint32_t*)(pBh + j * 8 * PITCH + kb + 16);
                blf[j][0] = *(const uint32_t*)(pBl + j * 8 * PITCH + kb);
                blf[j][1] = *(const uint32_t*)(pBl + j * 8 * PITCH + kb + 16);
            }
            #pragma unroll
            for (int mt = 0; mt < 2; mt++)
                #pragma unroll
                for (int j = 0; j < 4; j++) {
                    mma_f16(acc[mt][j][0], acc[mt][j][1], acc[mt][j][2], acc[mt][j][3],
                            ah[mt][0], ah[mt][1], ah[mt][2], ah[mt][3], bhf[j][0], bhf[j][1]);
                    mma_f16(acc[mt][j][0], acc[mt][j][1], acc[mt][j][2], acc[mt][j][3],
                            ah[mt][0], ah[mt][1], ah[mt][2], ah[mt][3], blf[j][0], blf[j][1]);
                }
        }
    }

    #pragma unroll
    for (int j = 0; j < 4; j++) {
        int col = c0 + wn + j * 8 + q * 2;
        float bi0 = b_in[col] + b_hh[col];
        float bi1 = b_in[col + 1] + b_hh[col + 1];
        #pragma unroll
        for (int mt = 0; mt < 2; mt++) {
            int row = r0 + wm + mt * 16 + gq;
            float2 n0 = __ldcg((const float2*)(noise + (size_t)row * H_SZ + col));
            float2 n1 = __ldcg((const float2*)(noise + (size_t)(row + 8) * H_SZ + col));
            float2 v0, v1;
            v0.x = ALPHA_F * (acc[mt][j][0] + bi0) + NSCALE * n0.x;
            v0.y = ALPHA_F * (acc[mt][j][1] + bi1) + NSCALE * n0.y;
            v1.x = ALPHA_F * (acc[mt][j][2] + bi0) + NSCALE * n1.x;
            v1.y = ALPHA_F * (acc[mt][j][3] + bi1) + NSCALE * n1.y;
            *(float2*)(g_c + (size_t)row * H_SZ + col) = v0;
            *(float2*)(g_c + (size_t)(row + 8) * H_SZ + col) = v1;
        }
    }
}

// ---- grid barrier: atomic arrival + per-CTA-line release (R13 proven) ------
__device__ __forceinline__ void grid_bar(int cta, unsigned epoch, unsigned* smflag) {
    __syncthreads();
    if (threadIdx.x == 0) {
        __threadfence();
        unsigned arrived = atomicAdd(&g_bar_count, 1u) + 1u;
        *smflag = (arrived == epoch * (unsigned)GRID_RNN) ? 1u : 0u;
    }
    __syncthreads();
    if (*smflag) {
        if (threadIdx.x < GRID_RNN) {
            *(volatile unsigned*)&g_rel[threadIdx.x * 32] = epoch;
        }
    } else if (threadIdx.x == 0) {
        while (*(volatile unsigned*)&g_rel[cta * 32] < epoch) { }
        __threadfence();
    }
    __syncthreads();
}

// ---------------- persistent recurrent kernel: full-K, no split, 1 barrier --
// 128 CTAs = 4 m-tiles x 32 n-tiles of 32x32. W slice resident (fp16 hi/lo).
// 8 warps = 2m x 4n of 16x8 tiles; 4 accumulator chains (kk parity x hi/lo).
// Update runs on fragments in registers; one grid barrier per step.
__global__ void __launch_bounds__(256, 1) rnn_kernel(
    float* __restrict__ hid_list, float* __restrict__ h_final,
    const float* __restrict__ w_hh, const float* __restrict__ hidden0)
{
    extern __shared__ char sm[];
    __shared__ unsigned smflag;
    const int cta = blockIdx.x;
    const int m0 = (cta >> 5) * 32;       // batch tile
    const int n0 = (cta & 31) * 32;       // output-column tile
    const int tid = threadIdx.x;

    // resident weight slice: rows n0..n0+31, full K -> fp16 hi/lo
    for (int e = tid; e < 32 * 1024; e += 256) {
        int n = e >> 10, k = e & 1023;
        float w = w_hh[(size_t)(n0 + n) * H_SZ + k];
        __half wh = __float2half(w);
        __half wl = __float2half(w - __half2float(wh));
        *(__half*)(sm + B_HI + n * APITCH + k * 2) = wh;
        *(__half*)(sm + B_LO + n * APITCH + k * 2) = wl;
    }
    __syncthreads();

    const int wid = tid >> 5, lane = tid & 31;
    const int wm = (wid & 1) * 16;        // 2 m-stripes of 16
    const int wn = (wid >> 1) * 8;        // 4 n-stripes of 8
    const int gq = lane >> 2;
    const int q  = lane & 3;

    const char* pA  = sm + A_SM + (wm + gq) * APITCH + q * 4;
    const char* pBh = sm + B_HI + (wn + gq) * APITCH + q * 4;
    const char* pBl = sm + B_LO + (wn + gq) * APITCH + q * 4;

    // fragment-owned elements: rows r, r+8; cols c, c+1
    const int fr = m0 + wm + gq;
    const int fc = n0 + wn + q * 2;

    // h in registers, fragment layout
    float h0x = hidden0[(size_t)fr * H_SZ + fc];
    float h0y = hidden0[(size_t)fr * H_SZ + fc + 1];
    float h1x = hidden0[(size_t)(fr + 8) * H_SZ + fc];
    float h1y = hidden0[(size_t)(fr + 8) * H_SZ + fc + 1];

    unsigned epoch = 0;

    for (int t = 0; t < T_LEN; t++) {
        // prefetch c for owned elements
        float2 cv0 = __ldcg((const float2*)(g_c + (size_t)t * BH + (size_t)fr * H_SZ + fc));
        float2 cv1 = __ldcg((const float2*)(g_c + (size_t)t * BH + (size_t)(fr + 8) * H_SZ + fc));

        // stage A: 32 rows x 1024 fp16 = 64KB
        #pragma unroll
        for (int i = 0; i < 16; i++) {
            int idx = i * 256 + tid;              // 0..4095 uint4 units
            int r = idx >> 7, cc = idx & 127;
            uint4 v = __ldcg((const uint4*)((const char*)g_a + (size_t)(m0 + r) * 2048 + cc * 16));
            *(uint4*)(sm + A_SM + r * APITCH + cc * 16) = v;
        }
        __syncthreads();

        // full-K GEMM: 4 independent accumulator chains
        float aH[2][4] = {}, aL[2][4] = {};
        #pragma unroll 8
        for (int kk = 0; kk < 64; kk++) {
            const int kb = kk * 32;
            const int p = kk & 1;
            uint32_t a0 = *(const uint32_t*)(pA + kb);
            uint32_t a1 = *(const uint32_t*)(pA + 8 * APITCH + kb);
            uint32_t a2 = *(const uint32_t*)(pA + kb + 16);
            uint32_t a3 = *(const uint32_t*)(pA + 8 * APITCH + kb + 16);
            uint32_t bh0 = *(const uint32_t*)(pBh + kb);
            uint32_t bh1 = *(const uint32_t*)(pBh + kb + 16);
            uint32_t bl0 = *(const uint32_t*)(pBl + kb);
            uint32_t bl1 = *(const uint32_t*)(pBl + kb + 16);
            mma_f16(aH[p][0], aH[p][1], aH[p][2], aH[p][3], a0, a1, a2, a3, bh0, bh1);
            mma_f16(aL[p][0], aL[p][1], aL[p][2], aL[p][3], a0, a1, a2, a3, bl0, bl1);
        }
        __syncthreads();   // A buffer reused next step only after barrier, but keep fragment reads done

        // update in registers: h' = 0.75h + 0.25*tmp + c
        float f0 = aH[0][0] + aH[1][0] + aL[0][0] + aL[1][0];
        float f1 = aH[0][1] + aH[1][1] + aL[0][1] + aL[1][1];
        float f2 = aH[0][2] + aH[1][2] + aL[0][2] + aL[1][2];
        float f3 = aH[0][3] + aH[1][3] + aL[0][3] + aL[1][3];

        h0x = LEAK_F * h0x + ALPHA_F * f0 + cv0.x;
        h0y = LEAK_F * h0y + ALPHA_F * f1 + cv0.y;
        h1x = LEAK_F * h1x + ALPHA_F * f2 + cv1.x;
        h1y = LEAK_F * h1y + ALPHA_F * f3 + cv1.y;

        *(float2*)(hid_list + ((size_t)fr * T_LEN + t) * H_SZ + fc) = make_float2(h0x, h0y);
        *(float2*)(hid_list + ((size_t)(fr + 8) * T_LEN + t) * H_SZ + fc) = make_float2(h1x, h1y);
        if (t == T_LEN - 1) {
            *(float2*)(h_final + (size_t)fr * H_SZ + fc) = make_float2(h0x, h0y);
            *(float2*)(h_final + (size_t)(fr + 8) * H_SZ + fc) = make_float2(h1x, h1y);
        }

        float t0 = tanhf(h0x), t1 = tanhf(h0y), t2 = tanhf(h1x), t3 = tanhf(h1y);
        *(uint32_t*)((char*)g_a + ((size_t)fr * H_SZ + fc) * 2) = pack_h2(t0, t1);
        *(uint32_t*)((char*)g_a + ((size_t)(fr + 8) * H_SZ + fc) * 2) = pack_h2(t2, t3);

        grid_bar(cta, ++epoch, &smflag);
    }
}

// ------- post (tensor cores, R13 proven) --------------------------------------
__global__ void __launch_bounds__(256, 1) post_tc_kernel(
    const float* __restrict__ hid_list, const float* __restrict__ w_out,
    const float* __restrict__ b_out, float* __restrict__ out_list)
{
    extern __shared__ char sm[];
    const int tid = threadIdx.x;
    const int c0 = blockIdx.x * 64;
    const int r0 = blockIdx.y * 128;
    const int wid = tid >> 5, lane = tid & 31;
    const int wm = (wid & 3) * 32;
    const int wn = (wid >> 2) * 32;
    const int gq = lane >> 2, q = lane & 3;

    float acc[2][4][4] = {};
    const char* pA  = sm + P_A  + (wm + gq) * PITCH + q * 4;
    const char* pBh = sm + P_BH + (wn + gq) * PITCH + q * 4;
    const char* pBl = sm + P_BL + (wn + gq) * PITCH + q * 4;

    for (int ch = 0; ch < 16; ch++) {
        const int kc = ch * 64;
        __syncthreads();
        #pragma unroll
        for (int i = 0; i < 8; i++) {
            int idx = i * 256 + tid;
            int r = idx >> 4, c4 = idx & 15;
            float4 v = __ldcg((const float4*)(hid_list + (size_t)(r0 + r) * H_SZ + kc + c4 * 4));
            *(uint2*)(sm + P_A + r * PITCH + c4 * 8) =
                make_uint2(pack_h2(v.x, v.y), pack_h2(v.z, v.w));
        }
        #pragma unroll
        for (int i = 0; i < 4; i++) {
            int idx = i * 256 + tid;
            int r = idx >> 4, c4 = idx & 15;
            float4 v = __ldcg((const float4*)(w_out + (size_t)(c0 + r) * H_SZ + kc + c4 * 4));
            float hx = __half2float(__float2half(v.x));
            float hy = __half2float(__float2half(v.y));
            float hz = __half2float(__float2half(v.z));
            float hw = __half2float(__float2half(v.w));
            *(uint2*)(sm + P_BH + r * PITCH + c4 * 8) =
                make_uint2(pack_h2(v.x, v.y), pack_h2(v.z, v.w));
            *(uint2*)(sm + P_BL + r * PITCH + c4 * 8) =
                make_uint2(pack_h2(v.x - hx, v.y - hy), pack_h2(v.z - hz, v.w - hw));
        }
        __syncthreads();

        #pragma unroll
        for (int kk = 0; kk < 4; kk++) {
            const int kb = kk * 32;
            uint32_t ah[2][4], bhf[4][2], blf[4][2];
            #pragma unroll
            for (int mt = 0; mt < 2; mt++) {
                const int mo = mt * 16 * PITCH;
                ah[mt][0] = *(const uint32_t*)(pA + mo + kb);
                ah[mt][1] = *(const uint32_t*)(pA + mo + 8 * PITCH + kb);
                ah[mt][2] = *(const uint32_t*)(pA + mo + kb + 16);
                ah[mt][3] = *(const uint32_t*)(pA + mo + 8 * PITCH + kb + 16);
            }
            #pragma unroll
            for (int j = 0; j < 4; j++) {
                bhf[j][0] = *(const uint32_t*)(pBh + j * 8 * PITCH + kb);
                bhf[j][1] = *(const uint32_t*)(pBh + j * 8 * PITCH + kb + 16);
                blf[j][0] = *(const uint32_t*)(pBl + j * 8 * PITCH + kb);
                blf[j][1] = *(const uint32_t*)(pBl + j * 8 * PITCH + kb + 16);
            }
            #pragma unroll
            for (int mt = 0; mt < 2; mt++)
                #pragma unroll
                for (int j = 0; j < 4; j++) {
                    mma_f16(acc[mt][j][0], acc[mt][j][1], acc[mt][j][2], acc[mt][j][3],
                            ah[mt][0], ah[mt][1], ah[mt][2], ah[mt][3], bhf[j][0], bhf[j][1]);
                    mma_f16(acc[mt][j][0], acc[mt][j][1], acc[mt][j][2], acc[mt][j][3],
                            ah[mt][0], ah[mt][1], ah[mt][2], ah[mt][3], blf[j][0], blf[j][1]);
                }
        }
    }

    #pragma unroll
    for (int mt = 0; mt < 2; mt++) {
        #pragma unroll
        for (int j = 0; j < 4; j++) {
            int col = c0 + wn + j * 8 + q * 2;
            float b0 = b_out[col], b1 = b_out[col + 1];
            int row = r0 + wm + mt * 16 + gq;
            float2 v0, v1;
            v0.x = fminf(fmaxf(acc[mt][j][0] + b0, -20.0f), 20.0f);
            v0.y = fminf(fmaxf(acc[mt][j][1] + b1, -20.0f), 20.0f);
            v1.x = fminf(fmaxf(acc[mt][j][2] + b0, -20.0f), 20.0f);
            v1.y = fminf(fmaxf(acc[mt][j][3] + b1, -20.0f), 20.0f);
            *(float2*)(out_list + (size_t)row * NOUT + col) = v0;
            *(float2*)(out_list + (size_t)(row + 8) * NOUT + col) = v1;
        }
    }
}

extern "C" void kernel_launch(void* const* d_in, const int* in_sizes, int n_in,
                              void* d_out, int out_size) {
    const float* x       = (const float*)d_in[0];
    const float* hidden0 = (const float*)d_in[1];
    const float* noise   = (const float*)d_in[2];
    const float* w_in_w  = (const float*)d_in[3];
    const float* w_in_b  = (const float*)d_in[4];
    const float* w_hh_w  = (const float*)d_in[5];
    const float* w_hh_b  = (const float*)d_in[6];
    const float* w_out_w = (const float*)d_in[7];
    const float* w_out_b = (const float*)d_in[8];

    float* out      = (float*)d_out;
    float* hid_list = out;
    float* out_list = out + (size_t)B_SZ * T_LEN * H_SZ;
    float* h_final  = out_list + (size_t)B_SZ * T_LEN * NOUT;

    cudaFuncSetAttribute(rnn_kernel, cudaFuncAttributeMaxDynamicSharedMemorySize, SM_ALLOC);
    cudaFuncSetAttribute(pre_tc_kernel, cudaFuncAttributeMaxDynamicSharedMemorySize, P_SMEM);
    cudaFuncSetAttribute(post_tc_kernel, cudaFuncAttributeMaxDynamicSharedMemorySize, P_SMEM);
    init_kernel<<<(BH + 255) / 256, 256>>>(hidden0);
    pre_tc_kernel<<<dim3(H_SZ / 64, (T_LEN * B_SZ) / 128), 256, P_SMEM>>>(
        x, noise, w_in_w, w_in_b, w_hh_b);
    rnn_kernel<<<GRID_RNN, 256, SM_ALLOC>>>(hid_list, h_final, w_hh_w, hidden0);
    post_tc_kernel<<<dim3(NOUT / 64, (B_SZ * T_LEN) / 128), 256, P_SMEM>>>(
        hid_list, w_out_w, w_out_b, out_list);
}

// round 16
// speedup vs baseline: 1.5599x; 1.0160x over previous
#include <cuda_runtime.h>
#include <cuda_fp16.h>
#include <math.h>
#include <stdint.h>

#define T_LEN   512
#define B_SZ    128
#define H_SZ    1024
#define NIN     128
#define NOUT    128
#define ALPHA_F 0.25f
#define LEAK_F  0.75f
#define NSCALE  0.025f
#define BH      (B_SZ * H_SZ)

// rnn SMEM: A 32 rows x 2064B (fp16, full K=1024); B 32 x 2064 hi+lo
#define APITCH 2064
#define A_SM   0
#define B_HI   66048
#define B_LO   132096
#define SM_ALLOC 198144

// pre/post SMEM (proven): A single (128 x 528), B hi+lo (64 x 528 each)
#define PITCH  528
#define P_A    0
#define P_BH   67584
#define P_BL   101376
#define P_SMEM 135168

// ---------------- device scratch ----------------
__device__ float g_c[(size_t)T_LEN * BH];
__device__ __half g_a[2][BH];                    // tanh(h) fp16, double buffered
__device__ unsigned g_cnt[4 * 32];               // per-m-group arrival counter (own line)
__device__ unsigned g_rel[128 * 32];             // per-CTA release word (own line)

__device__ __forceinline__ void mma_f16(float& c0, float& c1, float& c2, float& c3,
                                        uint32_t a0, uint32_t a1, uint32_t a2, uint32_t a3,
                                        uint32_t b0, uint32_t b1) {
    asm volatile(
        "mma.sync.aligned.m16n8k16.row.col.f32.f16.f16.f32 "
        "{%0,%1,%2,%3}, {%4,%5,%6,%7}, {%8,%9}, {%0,%1,%2,%3};"
        : "+f"(c0), "+f"(c1), "+f"(c2), "+f"(c3)
        : "r"(a0), "r"(a1), "r"(a2), "r"(a3), "r"(b0), "r"(b1));
}

__device__ __forceinline__ uint32_t pack_h2(float a, float b) {
    __half x = __float2half(a), y = __float2half(b);
    return (uint32_t)__half_as_ushort(x) | ((uint32_t)__half_as_ushort(y) << 16);
}

// ---------------- init ----------------
__global__ void init_kernel(const float* __restrict__ hidden) {
    int i = blockIdx.x * blockDim.x + threadIdx.x;
    if (i < 4 * 32) g_cnt[i] = 0u;
    if (i < 128 * 32) g_rel[i] = 0u;
    if (i < BH) g_a[0][i] = __float2half(tanhf(hidden[i]));
}

// ------- pre (tensor cores, proven) ------------------------------------------
__global__ void __launch_bounds__(256, 1) pre_tc_kernel(
    const float* __restrict__ x, const float* __restrict__ noise,
    const float* __restrict__ w_in, const float* __restrict__ b_in,
    const float* __restrict__ b_hh)
{
    extern __shared__ char sm[];
    const int tid = threadIdx.x;
    const int c0 = blockIdx.x * 64;
    const int r0 = blockIdx.y * 128;
    const int wid = tid >> 5, lane = tid & 31;
    const int wm = (wid & 3) * 32;
    const int wn = (wid >> 2) * 32;
    const int gq = lane >> 2, q = lane & 3;

    float acc[2][4][4] = {};
    const char* pA  = sm + P_A  + (wm + gq) * PITCH + q * 4;
    const char* pBh = sm + P_BH + (wn + gq) * PITCH + q * 4;
    const char* pBl = sm + P_BL + (wn + gq) * PITCH + q * 4;

    #pragma unroll
    for (int ch = 0; ch < 2; ch++) {
        const int kc = ch * 64;
        __syncthreads();
        #pragma unroll
        for (int i = 0; i < 8; i++) {
            int idx = i * 256 + tid;
            int r = idx >> 4, c4 = idx & 15;
            int rr = r0 + r;
            const float* src = x + ((size_t)(rr & 127) * T_LEN + (rr >> 7)) * NIN + kc + c4 * 4;
            float4 v = __ldcg((const float4*)src);
            *(uint2*)(sm + P_A + r * PITCH + c4 * 8) =
                make_uint2(pack_h2(v.x, v.y), pack_h2(v.z, v.w));
        }
        #pragma unroll
        for (int i = 0; i < 4; i++) {
            int idx = i * 256 + tid;
            int r = idx >> 4, c4 = idx & 15;
            float4 v = __ldcg((const float4*)(w_in + (size_t)(c0 + r) * NIN + kc + c4 * 4));
            float hx = __half2float(__float2half(v.x));
            float hy = __half2float(__float2half(v.y));
            float hz = __half2float(__float2half(v.z));
            float hw = __half2float(__float2half(v.w));
            *(uint2*)(sm + P_BH + r * PITCH + c4 * 8) =
                make_uint2(pack_h2(v.x, v.y), pack_h2(v.z, v.w));
            *(uint2*)(sm + P_BL + r * PITCH + c4 * 8) =
                make_uint2(pack_h2(v.x - hx, v.y - hy), pack_h2(v.z - hz, v.w - hw));
        }
        __syncthreads();

        #pragma unroll
        for (int kk = 0; kk < 4; kk++) {
            const int kb = kk * 32;
            uint32_t ah[2][4], bhf[4][2], blf[4][2];
            #pragma unroll
            for (int mt = 0; mt < 2; mt++) {
                const int mo = mt * 16 * PITCH;
                ah[mt][0] = *(const uint32_t*)(pA + mo + kb);
                ah[mt][1] = *(const uint32_t*)(pA + mo + 8 * PITCH + kb);
                ah[mt][2] = *(const uint32_t*)(pA + mo + kb + 16);
                ah[mt][3] = *(const uint32_t*)(pA + mo + 8 * PITCH + kb + 16);
            }
            #pragma unroll
            for (int j = 0; j < 4; j++) {
                bhf[j][0] = *(const uint32_t*)(pBh + j * 8 * PITCH + kb);
                bhf[j][1] = *(const uint32_t*)(pBh + j * 8 * PITCH + kb + 16);
                blf[j][0] = *(const uint32_t*)(pBl + j * 8 * PITCH + kb);
                blf[j][1] = *(const uint32_t*)(pBl + j * 8 * PITCH + kb + 16);
            }
            #pragma unroll
            for (int mt = 0; mt < 2; mt++)
                #pragma unroll
                for (int j = 0; j < 4; j++) {
                    mma_f16(acc[mt][j][0], acc[mt][j][1], acc[mt][j][2], acc[mt][j][3],
                            ah[mt][0], ah[mt][1], ah[mt][2], ah[mt][3], bhf[j][0], bhf[j][1]);
                    mma_f16(acc[mt][j][0], acc[mt][j][1], acc[mt][j][2], acc[mt][j][3],
                            ah[mt][0], ah[mt][1], ah[mt][2], ah[mt][3], blf[j][0], blf[j][1]);
                }
        }
    }

    #pragma unroll
    for (int j = 0; j < 4; j++) {
        int col = c0 + wn + j * 8 + q * 2;
        float bi0 = b_in[col] + b_hh[col];
        float bi1 = b_in[col + 1] + b_hh[col + 1];
        #pragma unroll
        for (int mt = 0; mt < 2; mt++) {
            int row = r0 + wm + mt * 16 + gq;
            float2 n0 = __ldcg((const float2*)(noise + (size_t)row * H_SZ + col));
            float2 n1 = __ldcg((const float2*)(noise + (size_t)(row + 8) * H_SZ + col));
            float2 v0, v1;
            v0.x = ALPHA_F * (acc[mt][j][0] + bi0) + NSCALE * n0.x;
            v0.y = ALPHA_F * (acc[mt][j][1] + bi1) + NSCALE * n0.y;
            v1.x = ALPHA_F * (acc[mt][j][2] + bi0) + NSCALE * n1.x;
            v1.y = ALPHA_F * (acc[mt][j][3] + bi1) + NSCALE * n1.y;
            *(float2*)(g_c + (size_t)row * H_SZ + col) = v0;
            *(float2*)(g_c + (size_t)(row + 8) * H_SZ + col) = v1;
        }
    }
}

// ---- per-m-group barrier (32 CTAs): atomic arrival + per-CTA-line release --
__device__ __forceinline__ void group_bar(int mg, int cta, unsigned epoch, unsigned* smflag) {
    __syncthreads();
    if (threadIdx.x == 0) {
        __threadfence();
        unsigned arrived = atomicAdd(&g_cnt[mg * 32], 1u) + 1u;
        *smflag = (arrived == epoch * 32u) ? 1u : 0u;
    }
    __syncthreads();
    if (*smflag) {
        if (threadIdx.x < 32) {
            *(volatile unsigned*)&g_rel[(mg * 32 + threadIdx.x) * 32] = epoch;
        }
    } else if (threadIdx.x == 0) {
        while (*(volatile unsigned*)&g_rel[cta * 32] < epoch) { }
        __threadfence();
    }
    __syncthreads();
}

// ---------------- persistent recurrent kernel: full-K, group barriers -------
// 128 CTAs = 4 m-tiles x 32 n-tiles of 32x32. W slice resident (fp16 hi/lo).
// g_a double-buffered: read t&1, write (t&1)^1 — no read/write race.
__global__ void __launch_bounds__(256, 1) rnn_kernel(
    float* __restrict__ hid_list, float* __restrict__ h_final,
    const float* __restrict__ w_hh, const float* __restrict__ hidden0)
{
    extern __shared__ char sm[];
    __shared__ unsigned smflag;
    const int cta = blockIdx.x;
    const int mg = cta >> 5;              // m-group 0..3
    const int m0 = mg * 32;               // batch tile
    const int n0 = (cta & 31) * 32;       // output-column tile
    const int tid = threadIdx.x;

    // resident weight slice: rows n0..n0+31, full K -> fp16 hi/lo
    for (int e = tid; e < 32 * 1024; e += 256) {
        int n = e >> 10, k = e & 1023;
        float w = w_hh[(size_t)(n0 + n) * H_SZ + k];
        __half wh = __float2half(w);
        __half wl = __float2half(w - __half2float(wh));
        *(__half*)(sm + B_HI + n * APITCH + k * 2) = wh;
        *(__half*)(sm + B_LO + n * APITCH + k * 2) = wl;
    }
    __syncthreads();

    const int wid = tid >> 5, lane = tid & 31;
    const int wm = (wid & 1) * 16;        // 2 m-stripes of 16
    const int wn = (wid >> 1) * 8;        // 4 n-stripes of 8
    const int gq = lane >> 2;
    const int q  = lane & 3;

    const char* pA  = sm + A_SM + (wm + gq) * APITCH + q * 4;
    const char* pBh = sm + B_HI + (wn + gq) * APITCH + q * 4;
    const char* pBl = sm + B_LO + (wn + gq) * APITCH + q * 4;

    // fragment-owned elements: rows fr, fr+8; cols fc, fc+1
    const int fr = m0 + wm + gq;
    const int fc = n0 + wn + q * 2;

    float h0x = hidden0[(size_t)fr * H_SZ + fc];
    float h0y = hidden0[(size_t)fr * H_SZ + fc + 1];
    float h1x = hidden0[(size_t)(fr + 8) * H_SZ + fc];
    float h1y = hidden0[(size_t)(fr + 8) * H_SZ + fc + 1];

    unsigned epoch = 0;

    for (int t = 0; t < T_LEN; t++) {
        const int p = t & 1;
        const char* ga_r = (const char*)g_a[p];
        char* ga_w = (char*)g_a[p ^ 1];

        // prefetch c for owned elements
        float2 cv0 = __ldcg((const float2*)(g_c + (size_t)t * BH + (size_t)fr * H_SZ + fc));
        float2 cv1 = __ldcg((const float2*)(g_c + (size_t)t * BH + (size_t)(fr + 8) * H_SZ + fc));

        // stage A: 32 rows x 1024 fp16 = 64KB
        #pragma unroll
        for (int i = 0; i < 16; i++) {
            int idx = i * 256 + tid;
            int r = idx >> 7, cc = idx & 127;
            uint4 v = __ldcg((const uint4*)(ga_r + (size_t)(m0 + r) * 2048 + cc * 16));
            *(uint4*)(sm + A_SM + r * APITCH + cc * 16) = v;
        }
        __syncthreads();

        // full-K GEMM: 4 independent accumulator chains
        float aH[2][4] = {}, aL[2][4] = {};
        #pragma unroll 8
        for (int kk = 0; kk < 64; kk++) {
            const int kb = kk * 32;
            const int pp = kk & 1;
            uint32_t a0 = *(const uint32_t*)(pA + kb);
            uint32_t a1 = *(const uint32_t*)(pA + 8 * APITCH + kb);
            uint32_t a2 = *(const uint32_t*)(pA + kb + 16);
            uint32_t a3 = *(const uint32_t*)(pA + 8 * APITCH + kb + 16);
            uint32_t bh0 = *(const uint32_t*)(pBh + kb);
            uint32_t bh1 = *(const uint32_t*)(pBh + kb + 16);
            uint32_t bl0 = *(const uint32_t*)(pBl + kb);
            uint32_t bl1 = *(const uint32_t*)(pBl + kb + 16);
            mma_f16(aH[pp][0], aH[pp][1], aH[pp][2], aH[pp][3], a0, a1, a2, a3, bh0, bh1);
            mma_f16(aL[pp][0], aL[pp][1], aL[pp][2], aL[pp][3], a0, a1, a2, a3, bl0, bl1);
        }
        __syncthreads();

        // update in registers: h' = 0.75h + 0.25*tmp + c
        float f0 = aH[0][0] + aH[1][0] + aL[0][0] + aL[1][0];
        float f1 = aH[0][1] + aH[1][1] + aL[0][1] + aL[1][1];
        float f2 = aH[0][2] + aH[1][2] + aL[0][2] + aL[1][2];
        float f3 = aH[0][3] + aH[1][3] + aL[0][3] + aL[1][3];

        h0x = LEAK_F * h0x + ALPHA_F * f0 + cv0.x;
        h0y = LEAK_F * h0y + ALPHA_F * f1 + cv0.y;
        h1x = LEAK_F * h1x + ALPHA_F * f2 + cv1.x;
        h1y = LEAK_F * h1y + ALPHA_F * f3 + cv1.y;

        *(float2*)(hid_list + ((size_t)fr * T_LEN + t) * H_SZ + fc) = make_float2(h0x, h0y);
        *(float2*)(hid_list + ((size_t)(fr + 8) * T_LEN + t) * H_SZ + fc) = make_float2(h1x, h1y);
        if (t == T_LEN - 1) {
            *(float2*)(h_final + (size_t)fr * H_SZ + fc) = make_float2(h0x, h0y);
            *(float2*)(h_final + (size_t)(fr + 8) * H_SZ + fc) = make_float2(h1x, h1y);
        }

        float t0 = tanhf(h0x), t1 = tanhf(h0y), t2 = tanhf(h1x), t3 = tanhf(h1y);
        *(uint32_t*)(ga_w + ((size_t)fr * H_SZ + fc) * 2) = pack_h2(t0, t1);
        *(uint32_t*)(ga_w + ((size_t)(fr + 8) * H_SZ + fc) * 2) = pack_h2(t2, t3);

        group_bar(mg, cta, ++epoch, &smflag);
    }
}

// ------- post (tensor cores, proven) ------------------------------------------
__global__ void __launch_bounds__(256, 1) post_tc_kernel(
    const float* __restrict__ hid_list, const float* __restrict__ w_out,
    const float* __restrict__ b_out, float* __restrict__ out_list)
{
    extern __shared__ char sm[];
    const int tid = threadIdx.x;
    const int c0 = blockIdx.x * 64;
    const int r0 = blockIdx.y * 128;
    const int wid = tid >> 5, lane = tid & 31;
    const int wm = (wid & 3) * 32;
    const int wn = (wid >> 2) * 32;
    const int gq = lane >> 2, q = lane & 3;

    float acc[2][4][4] = {};
    const char* pA  = sm + P_A  + (wm + gq) * PITCH + q * 4;
    const char* pBh = sm + P_BH + (wn + gq) * PITCH + q * 4;
    const char* pBl = sm + P_BL + (wn + gq) * PITCH + q * 4;

    for (int ch = 0; ch < 16; ch++) {
        const int kc = ch * 64;
        __syncthreads();
        #pragma unroll
        for (int i = 0; i < 8; i++) {
            int idx = i * 256 + tid;
            int r = idx >> 4, c4 = idx & 15;
            float4 v = __ldcg((const float4*)(hid_list + (size_t)(r0 + r) * H_SZ + kc + c4 * 4));
            *(uint2*)(sm + P_A + r * PITCH + c4 * 8) =
                make_uint2(pack_h2(v.x, v.y), pack_h2(v.z, v.w));
        }
        #pragma unroll
        for (int i = 0; i < 4; i++) {
            int idx = i * 256 + tid;
            int r = idx >> 4, c4 = idx & 15;
            float4 v = __ldcg((const float4*)(w_out + (size_t)(c0 + r) * H_SZ + kc + c4 * 4));
            float hx = __half2float(__float2half(v.x));
            float hy = __half2float(__float2half(v.y));
            float hz = __half2float(__float2half(v.z));
            float hw = __half2float(__float2half(v.w));
            *(uint2*)(sm + P_BH + r * PITCH + c4 * 8) =
                make_uint2(pack_h2(v.x, v.y), pack_h2(v.z, v.w));
            *(uint2*)(sm + P_BL + r * PITCH + c4 * 8) =
                make_uint2(pack_h2(v.x - hx, v.y - hy), pack_h2(v.z - hz, v.w - hw));
        }
        __syncthreads();

        #pragma unroll
        for (int kk = 0; kk < 4; kk++) {
            const int kb = kk * 32;
            uint32_t ah[2][4], bhf[4][2], blf[4][2];
            #pragma unroll
            for (int mt = 0; mt < 2; mt++) {
                const int mo = mt * 16 * PITCH;
                ah[mt][0] = *(const uint32_t*)(pA + mo + kb);
                ah[mt][1] = *(const uint32_t*)(pA + mo + 8 * PITCH + kb);
                ah[mt][2] = *(const uint32_t*)(pA + mo + kb + 16);
                ah[mt][3] = *(const uint32_t*)(pA + mo + 8 * PITCH + kb + 16);
            }
            #pragma unroll
            for (int j = 0; j < 4; j++) {
                bhf[j][0] = *(const uint32_t*)(pBh + j * 8 * PITCH + kb);
                bhf[j][1] = *(const uint32_t*)(pBh + j * 8 * PITCH + kb + 16);
                blf[j][0] = *(const uint32_t*)(pBl + j * 8 * PITCH + kb);
                blf[j][1] = *(const uint32_t*)(pBl + j * 8 * PITCH + kb + 16);
            }
            #pragma unroll
            for (int mt = 0; mt < 2; mt++)
                #pragma unroll
                for (int j = 0; j < 4; j++) {
                    mma_f16(acc[mt][j][0], acc[mt][j][1], acc[mt][j][2], acc[mt][j][3],
                            ah[mt][0], ah[mt][1], ah[mt][2], ah[mt][3], bhf[j][0], bhf[j][1]);
                    mma_f16(acc[mt][j][0], acc[mt][j][1], acc[mt][j][2], acc[mt][j][3],
                            ah[mt][0], ah[mt][1], ah[mt][2], ah[mt][3], blf[j][0], blf[j][1]);
                }
        }
    }

    #pragma unroll
    for (int mt = 0; mt < 2; mt++) {
        #pragma unroll
        for (int j = 0; j < 4; j++) {
            int col = c0 + wn + j * 8 + q * 2;
            float b0 = b_out[col], b1 = b_out[col + 1];
            int row = r0 + wm + mt * 16 + gq;
            float2 v0, v1;
            v0.x = fminf(fmaxf(acc[mt][j][0] + b0, -20.0f), 20.0f);
            v0.y = fminf(fmaxf(acc[mt][j][1] + b1, -20.0f), 20.0f);
            v1.x = fminf(fmaxf(acc[mt][j][2] + b0, -20.0f), 20.0f);
            v1.y = fminf(fmaxf(acc[mt][j][3] + b1, -20.0f), 20.0f);
            *(float2*)(out_list + (size_t)row * NOUT + col) = v0;
            *(float2*)(out_list + (size_t)(row + 8) * NOUT + col) = v1;
        }
    }
}

extern "C" void kernel_launch(void* const* d_in, const int* in_sizes, int n_in,
                              void* d_out, int out_size) {
    const float* x       = (const float*)d_in[0];
    const float* hidden0 = (const float*)d_in[1];
    const float* noise   = (const float*)d_in[2];
    const float* w_in_w  = (const float*)d_in[3];
    const float* w_in_b  = (const float*)d_in[4];
    const float* w_hh_w  = (const float*)d_in[5];
    const float* w_hh_b  = (const float*)d_in[6];
    const float* w_out_w = (const float*)d_in[7];
    const float* w_out_b = (const float*)d_in[8];

    float* out      = (float*)d_out;
    float* hid_list = out;
    float* out_list = out + (size_t)B_SZ * T_LEN * H_SZ;
    float* h_final  = out_list + (size_t)B_SZ * T_LEN * NOUT;

    cudaFuncSetAttribute(rnn_kernel, cudaFuncAttributeMaxDynamicSharedMemorySize, SM_ALLOC);
    cudaFuncSetAttribute(pre_tc_kernel, cudaFuncAttributeMaxDynamicSharedMemorySize, P_SMEM);
    cudaFuncSetAttribute(post_tc_kernel, cudaFuncAttributeMaxDynamicSharedMemorySize, P_SMEM);
    init_kernel<<<(BH + 255) / 256, 256>>>(hidden0);
    pre_tc_kernel<<<dim3(H_SZ / 64, (T_LEN * B_SZ) / 128), 256, P_SMEM>>>(
        x, noise, w_in_w, w_in_b, w_hh_b);
    rnn_kernel<<<128, 256, SM_ALLOC>>>(hid_list, h_final, w_hh_w, hidden0);
    post_tc_kernel<<<dim3(NOUT / 64, (B_SZ * T_LEN) / 128), 256, P_SMEM>>>(
        hid_list, w_out_w, w_out_b, out_list);
}

// round 17
// speedup vs baseline: 1.7261x; 1.1065x over previous
#include <cuda_runtime.h>
#include <cuda_fp16.h>
#include <math.h>
#include <stdint.h>

#define T_LEN   512
#define B_SZ    128
#define H_SZ    1024
#define NIN     128
#define NOUT    128
#define ALPHA_F 0.25f
#define LEAK_F  0.75f
#define NSCALE  0.025f
#define BH      (B_SZ * H_SZ)

// rnn SMEM: A 32 rows x 2064B (fp16, full K=1024); B 32 x 2064 (single fp16)
#define APITCH 2064
#define A_SM   0
#define B_HI   66048
#define SM_ALLOC 132096

// pre/post SMEM (proven): A single (128 x 528), B hi+lo (64 x 528 each)
#define PITCH  528
#define P_A    0
#define P_BH   67584
#define P_BL   101376
#define P_SMEM 135168

// ---------------- device scratch ----------------
__device__ float g_c[(size_t)T_LEN * BH];
__device__ __half g_a[2][BH];                    // tanh(h) fp16, double buffered
__device__ unsigned g_cnt[4 * 32];               // per-m-group arrival counter
__device__ unsigned g_rel[128 * 32];             // per-CTA release word (own line)

__device__ __forceinline__ void mma_f16(float& c0, float& c1, float& c2, float& c3,
                                        uint32_t a0, uint32_t a1, uint32_t a2, uint32_t a3,
                                        uint32_t b0, uint32_t b1) {
    asm volatile(
        "mma.sync.aligned.m16n8k16.row.col.f32.f16.f16.f32 "
        "{%0,%1,%2,%3}, {%4,%5,%6,%7}, {%8,%9}, {%0,%1,%2,%3};"
        : "+f"(c0), "+f"(c1), "+f"(c2), "+f"(c3)
        : "r"(a0), "r"(a1), "r"(a2), "r"(a3), "r"(b0), "r"(b1));
}

__device__ __forceinline__ uint32_t pack_h2(float a, float b) {
    __half x = __float2half(a), y = __float2half(b);
    return (uint32_t)__half_as_ushort(x) | ((uint32_t)__half_as_ushort(y) << 16);
}

// ---------------- init ----------------
__global__ void init_kernel(const float* __restrict__ hidden) {
    int i = blockIdx.x * blockDim.x + threadIdx.x;
    if (i < 4 * 32) g_cnt[i] = 0u;
    if (i < 128 * 32) g_rel[i] = 0u;
    if (i < BH) g_a[0][i] = __float2half(tanhf(hidden[i]));
}

// ------- pre (tensor cores, proven 2-product) ---------------------------------
__global__ void __launch_bounds__(256, 1) pre_tc_kernel(
    const float* __restrict__ x, const float* __restrict__ noise,
    const float* __restrict__ w_in, const float* __restrict__ b_in,
    const float* __restrict__ b_hh)
{
    extern __shared__ char sm[];
    const int tid = threadIdx.x;
    const int c0 = blockIdx.x * 64;
    const int r0 = blockIdx.y * 128;
    const int wid = tid >> 5, lane = tid & 31;
    const int wm = (wid & 3) * 32;
    const int wn = (wid >> 2) * 32;
    const int gq = lane >> 2, q = lane & 3;

    float acc[2][4][4] = {};
    const char* pA  = sm + P_A  + (wm + gq) * PITCH + q * 4;
    const char* pBh = sm + P_BH + (wn + gq) * PITCH + q * 4;
    const char* pBl = sm + P_BL + (wn + gq) * PITCH + q * 4;

    #pragma unroll
    for (int ch = 0; ch < 2; ch++) {
        const int kc = ch * 64;
        __syncthreads();
        #pragma unroll
        for (int i = 0; i < 8; i++) {
            int idx = i * 256 + tid;
            int r = idx >> 4, c4 = idx & 15;
            int rr = r0 + r;
            const float* src = x + ((size_t)(rr & 127) * T_LEN + (rr >> 7)) * NIN + kc + c4 * 4;
            float4 v = __ldcg((const float4*)src);
            *(uint2*)(sm + P_A + r * PITCH + c4 * 8) =
                make_uint2(pack_h2(v.x, v.y), pack_h2(v.z, v.w));
        }
        #pragma unroll
        for (int i = 0; i < 4; i++) {
            int idx = i * 256 + tid;
            int r = idx >> 4, c4 = idx & 15;
            float4 v = __ldcg((const float4*)(w_in + (size_t)(c0 + r) * NIN + kc + c4 * 4));
            float hx = __half2float(__float2half(v.x));
            float hy = __half2float(__float2half(v.y));
            float hz = __half2float(__float2half(v.z));
            float hw = __half2float(__float2half(v.w));
            *(uint2*)(sm + P_BH + r * PITCH + c4 * 8) =
                make_uint2(pack_h2(v.x, v.y), pack_h2(v.z, v.w));
            *(uint2*)(sm + P_BL + r * PITCH + c4 * 8) =
                make_uint2(pack_h2(v.x - hx, v.y - hy), pack_h2(v.z - hz, v.w - hw));
        }
        __syncthreads();

        #pragma unroll
        for (int kk = 0; kk < 4; kk++) {
            const int kb = kk * 32;
            uint32_t ah[2][4], bhf[4][2], blf[4][2];
            #pragma unroll
            for (int mt = 0; mt < 2; mt++) {
                const int mo = mt * 16 * PITCH;
                ah[mt][0] = *(const uint32_t*)(pA + mo + kb);
                ah[mt][1] = *(const uint32_t*)(pA + mo + 8 * PITCH + kb);
                ah[mt][2] = *(const uint32_t*)(pA + mo + kb + 16);
                ah[mt][3] = *(const uint32_t*)(pA + mo + 8 * PITCH + kb + 16);
            }
            #pragma unroll
            for (int j = 0; j < 4; j++) {
                bhf[j][0] = *(const uint32_t*)(pBh + j * 8 * PITCH + kb);
                bhf[j][1] = *(const uint32_t*)(pBh + j * 8 * PITCH + kb + 16);
                blf[j][0] = *(const uint32_t*)(pBl + j * 8 * PITCH + kb);
                blf[j][1] = *(const uint32_t*)(pBl + j * 8 * PITCH + kb + 16);
            }
            #pragma unroll
            for (int mt = 0; mt < 2; mt++)
                #pragma unroll
                for (int j = 0; j < 4; j++) {
                    mma_f16(acc[mt][j][0], acc[mt][j][1], acc[mt][j][2], acc[mt][j][3],
                            ah[mt][0], ah[mt][1], ah[mt][2], ah[mt][3], bhf[j][0], bhf[j][1]);
                    mma_f16(acc[mt][j][0], acc[mt][j][1], acc[mt][j][2], acc[mt][j][3],
                            ah[mt][0], ah[mt][1], ah[mt][2], ah[mt][3], blf[j][0], blf[j][1]);
                }
        }
    }

    #pragma unroll
    for (int j = 0; j < 4; j++) {
        int col = c0 + wn + j * 8 + q * 2;
        float bi0 = b_in[col] + b_hh[col];
        float bi1 = b_in[col + 1] + b_hh[col + 1];
        #pragma unroll
        for (int mt = 0; mt < 2; mt++) {
            int row = r0 + wm + mt * 16 + gq;
            float2 n0 = __ldcg((const float2*)(noise + (size_t)row * H_SZ + col));
            float2 n1 = __ldcg((const float2*)(noise + (size_t)(row + 8) * H_SZ + col));
            float2 v0, v1;
            v0.x = ALPHA_F * (acc[mt][j][0] + bi0) + NSCALE * n0.x;
            v0.y = ALPHA_F * (acc[mt][j][1] + bi1) + NSCALE * n0.y;
            v1.x = ALPHA_F * (acc[mt][j][2] + bi0) + NSCALE * n1.x;
            v1.y = ALPHA_F * (acc[mt][j][3] + bi1) + NSCALE * n1.y;
            *(float2*)(g_c + (size_t)row * H_SZ + col) = v0;
            *(float2*)(g_c + (size_t)(row + 8) * H_SZ + col) = v1;
        }
    }
}

// ---- per-m-group barrier (32 CTAs, proven R16) ------------------------------
__device__ __forceinline__ void group_bar(int mg, int cta, unsigned epoch, unsigned* smflag) {
    __syncthreads();
    if (threadIdx.x == 0) {
        __threadfence();
        unsigned arrived = atomicAdd(&g_cnt[mg * 32], 1u) + 1u;
        *smflag = (arrived == epoch * 32u) ? 1u : 0u;
    }
    __syncthreads();
    if (*smflag) {
        if (threadIdx.x < 32) {
            *(volatile unsigned*)&g_rel[(mg * 32 + threadIdx.x) * 32] = epoch;
        }
    } else if (threadIdx.x == 0) {
        while (*(volatile unsigned*)&g_rel[cta * 32] < epoch) { }
        __threadfence();
    }
    __syncthreads();
}

// ---------------- persistent recurrent kernel: full-K, single fp16 product --
// 128 CTAs = 4 m-tiles x 32 n-tiles of 32x32. W slice resident (single fp16).
// 8 warps = 2m x 4n of 16x8 tiles; 4 accumulator chains (kk & 3).
__global__ void __launch_bounds__(256, 1) rnn_kernel(
    float* __restrict__ hid_list, float* __restrict__ h_final,
    const float* __restrict__ w_hh, const float* __restrict__ hidden0)
{
    extern __shared__ char sm[];
    __shared__ unsigned smflag;
    const int cta = blockIdx.x;
    const int mg = cta >> 5;
    const int m0 = mg * 32;
    const int n0 = (cta & 31) * 32;
    const int tid = threadIdx.x;

    // resident weight slice: rows n0..n0+31, full K -> single fp16
    for (int e = tid; e < 32 * 1024; e += 256) {
        int n = e >> 10, k = e & 1023;
        *(__half*)(sm + B_HI + n * APITCH + k * 2) =
            __float2half(w_hh[(size_t)(n0 + n) * H_SZ + k]);
    }
    __syncthreads();

    const int wid = tid >> 5, lane = tid & 31;
    const int wm = (wid & 1) * 16;
    const int wn = (wid >> 1) * 8;
    const int gq = lane >> 2;
    const int q  = lane & 3;

    const char* pA  = sm + A_SM + (wm + gq) * APITCH + q * 4;
    const char* pBh = sm + B_HI + (wn + gq) * APITCH + q * 4;

    const int fr = m0 + wm + gq;
    const int fc = n0 + wn + q * 2;

    float h0x = hidden0[(size_t)fr * H_SZ + fc];
    float h0y = hidden0[(size_t)fr * H_SZ + fc + 1];
    float h1x = hidden0[(size_t)(fr + 8) * H_SZ + fc];
    float h1y = hidden0[(size_t)(fr + 8) * H_SZ + fc + 1];

    unsigned epoch = 0;

    for (int t = 0; t < T_LEN; t++) {
        const int p = t & 1;
        const char* ga_r = (const char*)g_a[p];
        char* ga_w = (char*)g_a[p ^ 1];

        float2 cv0 = __ldcg((const float2*)(g_c + (size_t)t * BH + (size_t)fr * H_SZ + fc));
        float2 cv1 = __ldcg((const float2*)(g_c + (size_t)t * BH + (size_t)(fr + 8) * H_SZ + fc));

        // stage A: 32 rows x 1024 fp16 = 64KB
        #pragma unroll
        for (int i = 0; i < 16; i++) {
            int idx = i * 256 + tid;
            int r = idx >> 7, cc = idx & 127;
            uint4 v = __ldcg((const uint4*)(ga_r + (size_t)(m0 + r) * 2048 + cc * 16));
            *(uint4*)(sm + A_SM + r * APITCH + cc * 16) = v;
        }
        __syncthreads();

        // full-K GEMM, single product, 4 accumulator chains
        float ac[4][4] = {};
        #pragma unroll 8
        for (int kk = 0; kk < 64; kk++) {
            const int kb = kk * 32;
            const int pp = kk & 3;
            uint32_t a0 = *(const uint32_t*)(pA + kb);
            uint32_t a1 = *(const uint32_t*)(pA + 8 * APITCH + kb);
            uint32_t a2 = *(const uint32_t*)(pA + kb + 16);
            uint32_t a3 = *(const uint32_t*)(pA + 8 * APITCH + kb + 16);
            uint32_t b0 = *(const uint32_t*)(pBh + kb);
            uint32_t b1 = *(const uint32_t*)(pBh + kb + 16);
            mma_f16(ac[pp][0], ac[pp][1], ac[pp][2], ac[pp][3], a0, a1, a2, a3, b0, b1);
        }
        __syncthreads();

        float f0 = ac[0][0] + ac[1][0] + ac[2][0] + ac[3][0];
        float f1 = ac[0][1] + ac[1][1] + ac[2][1] + ac[3][1];
        float f2 = ac[0][2] + ac[1][2] + ac[2][2] + ac[3][2];
        float f3 = ac[0][3] + ac[1][3] + ac[2][3] + ac[3][3];

        h0x = LEAK_F * h0x + ALPHA_F * f0 + cv0.x;
        h0y = LEAK_F * h0y + ALPHA_F * f1 + cv0.y;
        h1x = LEAK_F * h1x + ALPHA_F * f2 + cv1.x;
        h1y = LEAK_F * h1y + ALPHA_F * f3 + cv1.y;

        *(float2*)(hid_list + ((size_t)fr * T_LEN + t) * H_SZ + fc) = make_float2(h0x, h0y);
        *(float2*)(hid_list + ((size_t)(fr + 8) * T_LEN + t) * H_SZ + fc) = make_float2(h1x, h1y);
        if (t == T_LEN - 1) {
            *(float2*)(h_final + (size_t)fr * H_SZ + fc) = make_float2(h0x, h0y);
            *(float2*)(h_final + (size_t)(fr + 8) * H_SZ + fc) = make_float2(h1x, h1y);
        }

        float t0 = tanhf(h0x), t1 = tanhf(h0y), t2 = tanhf(h1x), t3 = tanhf(h1y);
        *(uint32_t*)(ga_w + ((size_t)fr * H_SZ + fc) * 2) = pack_h2(t0, t1);
        *(uint32_t*)(ga_w + ((size_t)(fr + 8) * H_SZ + fc) * 2) = pack_h2(t2, t3);

        group_bar(mg, cta, ++epoch, &smflag);
    }
}

// ------- post (tensor cores, proven 2-product) ---------------------------------
__global__ void __launch_bounds__(256, 1) post_tc_kernel(
    const float* __restrict__ hid_list, const float* __restrict__ w_out,
    const float* __restrict__ b_out, float* __restrict__ out_list)
{
    extern __shared__ char sm[];
    const int tid = threadIdx.x;
    const int c0 = blockIdx.x * 64;
    const int r0 = blockIdx.y * 128;
    const int wid = tid >> 5, lane = tid & 31;
    const int wm = (wid & 3) * 32;
    const int wn = (wid >> 2) * 32;
    const int gq = lane >> 2, q = lane & 3;

    float acc[2][4][4] = {};
    const char* pA  = sm + P_A  + (wm + gq) * PITCH + q * 4;
    const char* pBh = sm + P_BH + (wn + gq) * PITCH + q * 4;
    const char* pBl = sm + P_BL + (wn + gq) * PITCH + q * 4;

    for (int ch = 0; ch < 16; ch++) {
        const int kc = ch * 64;
        __syncthreads();
        #pragma unroll
        for (int i = 0; i < 8; i++) {
            int idx = i * 256 + tid;
            int r = idx >> 4, c4 = idx & 15;
            float4 v = __ldcg((const float4*)(hid_list + (size_t)(r0 + r) * H_SZ + kc + c4 * 4));
            *(uint2*)(sm + P_A + r * PITCH + c4 * 8) =
                make_uint2(pack_h2(v.x, v.y), pack_h2(v.z, v.w));
        }
        #pragma unroll
        for (int i = 0; i < 4; i++) {
            int idx = i * 256 + tid;
            int r = idx >> 4, c4 = idx & 15;
            float4 v = __ldcg((const float4*)(w_out + (size_t)(c0 + r) * H_SZ + kc + c4 * 4));
            float hx = __half2float(__float2half(v.x));
            float hy = __half2float(__float2half(v.y));
            float hz = __half2float(__float2half(v.z));
            float hw = __half2float(__float2half(v.w));
            *(uint2*)(sm + P_BH + r * PITCH + c4 * 8) =
                make_uint2(pack_h2(v.x, v.y), pack_h2(v.z, v.w));
            *(uint2*)(sm + P_BL + r * PITCH + c4 * 8) =
                make_uint2(pack_h2(v.x - hx, v.y - hy), pack_h2(v.z - hz, v.w - hw));
        }
        __syncthreads();

        #pragma unroll
        for (int kk = 0; kk < 4; kk++) {
            const int kb = kk * 32;
            uint32_t ah[2][4], bhf[4][2], blf[4][2];
            #pragma unroll
            for (int mt = 0; mt < 2; mt++) {
                const int mo = mt * 16 * PITCH;
                ah[mt][0] = *(const uint32_t*)(pA + mo + kb);
                ah[mt][1] = *(const uint32_t*)(pA + mo + 8 * PITCH + kb);
                ah[mt][2] = *(const uint32_t*)(pA + mo + kb + 16);
                ah[mt][3] = *(const uint32_t*)(pA + mo + 8 * PITCH + kb + 16);
            }
            #pragma unroll
            for (int j = 0; j < 4; j++) {
                bhf[j][0] = *(const uint32_t*)(pBh + j * 8 * PITCH + kb);
                bhf[j][1] = *(const uint32_t*)(pBh + j * 8 * PITCH + kb + 16);
                blf[j][0] = *(const uint32_t*)(pBl + j * 8 * PITCH + kb);
                blf[j][1] = *(const uint32_t*)(pBl + j * 8 * PITCH + kb + 16);
            }
            #pragma unroll
            for (int mt = 0; mt < 2; mt++)
                #pragma unroll
                for (int j = 0; j < 4; j++) {
                    mma_f16(acc[mt][j][0], acc[mt][j][1], acc[mt][j][2], acc[mt][j][3],
                            ah[mt][0], ah[mt][1], ah[mt][2], ah[mt][3], bhf[j][0], bhf[j][1]);
                    mma_f16(acc[mt][j][0], acc[mt][j][1], acc[mt][j][2], acc[mt][j][3],
                            ah[mt][0], ah[mt][1], ah[mt][2], ah[mt][3], blf[j][0], blf[j][1]);
                }
        }
    }

    #pragma unroll
    for (int mt = 0; mt < 2; mt++) {
        #pragma unroll
        for (int j = 0; j < 4; j++) {
            int col = c0 + wn + j * 8 + q * 2;
            float b0 = b_out[col], b1 = b_out[col + 1];
            int row = r0 + wm + mt * 16 + gq;
            float2 v0, v1;
            v0.x = fminf(fmaxf(acc[mt][j][0] + b0, -20.0f), 20.0f);
            v0.y = fminf(fmaxf(acc[mt][j][1] + b1, -20.0f), 20.0f);
            v1.x = fminf(fmaxf(acc[mt][j][2] + b0, -20.0f), 20.0f);
            v1.y = fminf(fmaxf(acc[mt][j][3] + b1, -20.0f), 20.0f);
            *(float2*)(out_list + (size_t)row * NOUT + col) = v0;
            *(float2*)(out_list + (size_t)(row + 8) * NOUT + col) = v1;
        }
    }
}

extern "C" void kernel_launch(void* const* d_in, const int* in_sizes, int n_in,
                              void* d_out, int out_size) {
    const float* x       = (const float*)d_in[0];
    const float* hidden0 = (const float*)d_in[1];
    const float* noise   = (const float*)d_in[2];
    const float* w_in_w  = (const float*)d_in[3];
    const float* w_in_b  = (const float*)d_in[4];
    const float* w_hh_w  = (const float*)d_in[5];
    const float* w_hh_b  = (const float*)d_in[6];
    const float* w_out_w = (const float*)d_in[7];
    const float* w_out_b = (const float*)d_in[8];

    float* out      = (float*)d_out;
    float* hid_list = out;
    float* out_list = out + (size_t)B_SZ * T_LEN * H_SZ;
    float* h_final  = out_list + (size_t)B_SZ * T_LEN * NOUT;

    cudaFuncSetAttribute(rnn_kernel, cudaFuncAttributeMaxDynamicSharedMemorySize, SM_ALLOC);
    cudaFuncSetAttribute(pre_tc_kernel, cudaFuncAttributeMaxDynamicSharedMemorySize, P_SMEM);
    cudaFuncSetAttribute(post_tc_kernel, cudaFuncAttributeMaxDynamicSharedMemorySize, P_SMEM);
    init_kernel<<<(BH + 255) / 256, 256>>>(hidden0);
    pre_tc_kernel<<<dim3(H_SZ / 64, (T_LEN * B_SZ) / 128), 256, P_SMEM>>>(
        x, noise, w_in_w, w_in_b, w_hh_b);
    rnn_kernel<<<128, 256, SM_ALLOC>>>(hid_list, h_final, w_hh_w, hidden0);
    post_tc_kernel<<<dim3(NOUT / 64, (B_SZ * T_LEN) / 128), 256, P_SMEM>>>(
        hid_list, w_out_w, w_out_b, out_list);
}